// round 1
// baseline (speedup 1.0000x reference)
#include <cuda_runtime.h>

// LocalAttender fused kernel for GB300 (sm_103a).
// Shapes (fixed): guide [8,128,128,128] f32, value [8,128,64,64] f32,
//                 w_conv [9,128] f32, b_conv [9] f32, out [8,128,128,128] f32.
//
// One thread <-> one value-resolution "quad" (2x2 output pixels). The 9
// gathered value neighbors are shared by all 4 outputs of a quad.
// Packed f32x2 math: component0 = output col 2w, component1 = col 2w+1.
// acc[k][r] holds att (then softmaxed probs) for output row r of the quad.
//
// Block = 128 threads = 4 warps = 2 quad-sets x 2 channel-splits:
//   warp 0: set A (w 0..31),  c 0..63      warp 1: set A, c 64..127
//   warp 2: set B (w 32..63), c 0..63      warp 3: set B, c 64..127
// Grid = B*H = 8*64 = 512 blocks, block <-> (b, value-row h).

#define K9 9
#define CIN 128
#define HV 64
#define WV 64
#define HO 128
#define WO 128

__device__ __forceinline__ unsigned long long pk2(float lo, float hi) {
    unsigned long long d;
    asm("mov.b64 %0, {%1,%2};" : "=l"(d) : "f"(lo), "f"(hi));
    return d;
}
__device__ __forceinline__ void upk2(unsigned long long v, float& lo, float& hi) {
    asm("mov.b64 {%0,%1}, %2;" : "=f"(lo), "=f"(hi) : "l"(v));
}
__device__ __forceinline__ unsigned long long fma2(unsigned long long a,
                                                   unsigned long long b,
                                                   unsigned long long c) {
    unsigned long long d;
    asm("fma.rn.f32x2 %0, %1, %2, %3;" : "=l"(d) : "l"(a), "l"(b), "l"(c));
    return d;
}
__device__ __forceinline__ unsigned long long add2(unsigned long long a,
                                                   unsigned long long b) {
    unsigned long long d;
    asm("add.rn.f32x2 %0, %1, %2;" : "=l"(d) : "l"(a), "l"(b));
    return d;
}

__device__ __forceinline__ void softmax9(float a[K9]) {
    float m = a[0];
#pragma unroll
    for (int k = 1; k < K9; ++k) m = fmaxf(m, a[k]);
    float s = 0.0f;
#pragma unroll
    for (int k = 0; k < K9; ++k) { a[k] = __expf(a[k] - m); s += a[k]; }
    float inv = 1.0f / s;
#pragma unroll
    for (int k = 0; k < K9; ++k) a[k] *= inv;
}

__global__ __launch_bounds__(128, 4)
void la_fused_kernel(const float* __restrict__ guide,
                     const float* __restrict__ value,
                     const float* __restrict__ wconv,
                     const float* __restrict__ bconv,
                     float* __restrict__ out) {
    // pre-packed (w,w) pairs, indexed [c][k] so the per-c inner loop is contiguous
    __shared__ unsigned long long w2_s[CIN * K9];         // 9216 B
    __shared__ float b_s[K9];
    __shared__ unsigned long long part[4][32][2 * K9 + 1]; // partial att exchange, padded

    const int tid  = threadIdx.x;
    const int warp = tid >> 5;
    const int lane = tid & 31;

    // ---- phase 0: stage weights ----
    for (int i = tid; i < CIN * K9; i += 128) {
        int k = i / CIN, c = i - k * CIN;
        float v = wconv[i];
        w2_s[c * K9 + k] = pk2(v, v);
    }
    if (tid < K9) b_s[tid] = bconv[tid];
    __syncthreads();

    const int b     = blockIdx.x >> 6;
    const int h     = blockIdx.x & 63;
    const int cbase = (warp & 1) * 64;           // channel half
    const int wq    = ((warp >> 1) << 5) + lane; // value col 0..63

    unsigned long long acc[K9][2];
#pragma unroll
    for (int k = 0; k < K9; ++k) { acc[k][0] = 0ull; acc[k][1] = 0ull; }

    // ---- phase 1: att partial = sum_c w[k,c] * guide (+ residual for c<9) ----
    // guide pixel pair (2h, 2wq..2wq+1) loaded as one 64-bit word per row.
    const float* gp = guide + ((b * CIN + cbase) * HO + 2 * h) * WO + 2 * wq;
    const int GCS = HO * WO; // 16384, channel stride

    if (cbase == 0) {
        // first 9 channels also contribute the residual guide[:, :9]
#pragma unroll
        for (int c = 0; c < K9; ++c) {
            unsigned long long G0 = *(const unsigned long long*)(gp + c * GCS);
            unsigned long long G1 = *(const unsigned long long*)(gp + c * GCS + WO);
#pragma unroll
            for (int k = 0; k < K9; ++k) {
                unsigned long long W = w2_s[c * K9 + k];
                acc[k][0] = fma2(G0, W, acc[k][0]);
                acc[k][1] = fma2(G1, W, acc[k][1]);
            }
            acc[c][0] = add2(acc[c][0], G0);
            acc[c][1] = add2(acc[c][1], G1);
        }
#pragma unroll 2
        for (int c = K9; c < 64; ++c) {
            unsigned long long G0 = *(const unsigned long long*)(gp + c * GCS);
            unsigned long long G1 = *(const unsigned long long*)(gp + c * GCS + WO);
#pragma unroll
            for (int k = 0; k < K9; ++k) {
                unsigned long long W = w2_s[c * K9 + k];
                acc[k][0] = fma2(G0, W, acc[k][0]);
                acc[k][1] = fma2(G1, W, acc[k][1]);
            }
        }
    } else {
#pragma unroll 2
        for (int c = 0; c < 64; ++c) {
            unsigned long long G0 = *(const unsigned long long*)(gp + c * GCS);
            unsigned long long G1 = *(const unsigned long long*)(gp + c * GCS + WO);
#pragma unroll
            for (int k = 0; k < K9; ++k) {
                unsigned long long W = w2_s[(cbase + c) * K9 + k];
                acc[k][0] = fma2(G0, W, acc[k][0]);
                acc[k][1] = fma2(G1, W, acc[k][1]);
            }
        }
    }

    // ---- phase 1b: symmetric all-reduce of the two channel halves ----
#pragma unroll
    for (int k = 0; k < K9; ++k) {
        part[warp][lane][2 * k]     = acc[k][0];
        part[warp][lane][2 * k + 1] = acc[k][1];
    }
    __syncthreads();
    const int peer = warp ^ 1;
#pragma unroll
    for (int k = 0; k < K9; ++k) {
        acc[k][0] = add2(acc[k][0], part[peer][lane][2 * k]);
        acc[k][1] = add2(acc[k][1], part[peer][lane][2 * k + 1]);
    }

    // bias
#pragma unroll
    for (int k = 0; k < K9; ++k) {
        unsigned long long B = pk2(b_s[k], b_s[k]);
        acc[k][0] = add2(acc[k][0], B);
        acc[k][1] = add2(acc[k][1], B);
    }

    // ---- phase 2: softmax over k for each of the 4 quad pixels ----
#pragma unroll
    for (int r = 0; r < 2; ++r) {
        float a0[K9], a1[K9];
#pragma unroll
        for (int k = 0; k < K9; ++k) upk2(acc[k][r], a0[k], a1[k]);
        softmax9(a0);
        softmax9(a1);
#pragma unroll
        for (int k = 0; k < K9; ++k) acc[k][r] = pk2(a0[k], a1[k]);
    }

    // ---- phase 3: gather-weight-store over this warp's 64 channels ----
    const int ym1 = (h == 0) ? 0 : h - 1;
    const int yp1 = (h == HV - 1) ? HV - 1 : h + 1;
    const int xm1 = (wq == 0) ? 0 : wq - 1;
    const int xp1 = (wq == WV - 1) ? WV - 1 : wq + 1;
    const int ro[3] = { ym1 * WV, h * WV, yp1 * WV };
    const int co[3] = { xm1, wq, xp1 };

    const float* vp = value + (b * CIN + cbase) * (HV * WV);
    float* op = out + ((b * CIN + cbase) * HO + 2 * h) * WO + 2 * wq;
    const int VCS = HV * WV; // 4096

#pragma unroll 2
    for (int c = 0; c < 64; ++c) {
        const float* v = vp + c * VCS;
        unsigned long long o0 = 0ull, o1 = 0ull;
#pragma unroll
        for (int dy = 0; dy < 3; ++dy) {
#pragma unroll
            for (int dx = 0; dx < 3; ++dx) {
                float nv = __ldg(v + ro[dy] + co[dx]);
                unsigned long long NV = pk2(nv, nv);
                const int k = dy * 3 + dx;
                o0 = fma2(acc[k][0], NV, o0);
                o1 = fma2(acc[k][1], NV, o1);
            }
        }
        *(unsigned long long*)(op + c * GCS)      = o0;
        *(unsigned long long*)(op + c * GCS + WO) = o1;
    }
}

extern "C" void kernel_launch(void* const* d_in, const int* in_sizes, int n_in,
                              void* d_out, int out_size) {
    const float* guide = (const float*)d_in[0];
    const float* value = (const float*)d_in[1];
    const float* wconv = (const float*)d_in[2];
    const float* bconv = (const float*)d_in[3];
    float* out = (float*)d_out;
    (void)in_sizes; (void)n_in; (void)out_size;

    la_fused_kernel<<<512, 128>>>(guide, value, wconv, bconv, out);
}